// round 15
// baseline (speedup 1.0000x reference)
#include <cuda_runtime.h>
#include <cstdint>

#define BATCH 2048
#define D0 256
#define D1 256
#define D2 256
#define D3 128

// Scratch (device globals: allocation-free per harness rules)
__device__ float g_We0[D1 * D0];
__device__ float g_We1[D2 * D1];
__device__ float g_W2h[D2 * D3];   // [k][o] hi tf32 part of We2^T (bit patterns)
__device__ float g_W2l[D2 * D3];   // [k][o] lo tf32 part
__device__ float g_h1[BATCH * D1];
__device__ float g_h2[BATCH * D2];

__device__ __forceinline__ float tanh_fast(float x) {
    float y;
    asm("tanh.approx.f32 %0, %1;" : "=f"(y) : "f"(x));
    return y;
}

__device__ __forceinline__ unsigned int to_tf32(float f) {
    unsigned int r;
    asm("cvt.rna.tf32.f32 %0, %1;" : "=r"(r) : "f"(f));
    return r;
}

__device__ __forceinline__ float atom_apply(float w, int idx) {
    float v = w;                       // identity
    if (idx == 1)      v = sinf(w);
    else if (idx == 2) v = tanhf(w);
    else if (idx == 3) v = w * w;
    return v;
}

// Precompute effective weights. We2 stored transposed + hi/lo tf32 split.
__global__ void prep_we_kernel(const float* __restrict__ W0, const int* __restrict__ f0,
                               const float* __restrict__ W1, const int* __restrict__ f1,
                               const float* __restrict__ W2, const int* __restrict__ f2) {
    const int n01 = D1 * D0;           // 65536
    const int n2  = D3 * D2;           // 32768
    const int stride = gridDim.x * blockDim.x;
    for (int t = blockIdx.x * blockDim.x + threadIdx.x; t < n01; t += stride) {
        g_We0[t] = atom_apply(W0[t], f0[t]);
        g_We1[t] = atom_apply(W1[t], f1[t]);
    }
    for (int t = blockIdx.x * blockDim.x + threadIdx.x; t < n2; t += stride) {
        int o = t >> 8;                // W2 is [128][256] row-major
        int k = t & 255;
        float v = atom_apply(W2[t], f2[t]);
        unsigned int hb = to_tf32(v);
        float hf = __uint_as_float(hb);
        unsigned int lb = to_tf32(v - hf);
        g_W2h[k * D3 + o] = __uint_as_float(hb);
        g_W2l[k * D3 + o] = __uint_as_float(lb);
    }
}

// Hidden layer: h_out[b,o] = sum_i tanh(h[b,i]*We[o,i]) + bias[o]
// MUFU-bound, measured at floor — unchanged.
template <int IN>
__global__ __launch_bounds__(256) void layer_tanh_kernel(
    const float* __restrict__ h_in,   // [BATCH, IN]
    const float* __restrict__ We,     // [OUT, IN]
    const float* __restrict__ bias,   // [OUT]
    float* __restrict__ h_out,        // [BATCH, OUT]
    int OUT) {
    __shared__ float We_s[IN][33];
    __shared__ float h_s[8][IN];

    const int tx = threadIdx.x;
    const int ty = threadIdx.y;
    const int tid = ty * 32 + tx;
    const int o0 = blockIdx.x * 32;
    const int b0 = blockIdx.y * 8;

    for (int idx = tid; idx < 32 * IN; idx += 256) {
        int o = idx / IN;
        int i = idx - o * IN;
        We_s[i][o] = We[(o0 + o) * IN + i];
    }
    const float4* Hg = reinterpret_cast<const float4*>(h_in + b0 * IN);
    float4* Hs = reinterpret_cast<float4*>(&h_s[0][0]);
    for (int idx = tid; idx < 8 * IN / 4; idx += 256) {
        Hs[idx] = Hg[idx];
    }
    __syncthreads();

    float acc0 = 0.f, acc1 = 0.f;
#pragma unroll 8
    for (int i = 0; i < IN; i += 2) {
        float z0 = h_s[ty][i]     * We_s[i][tx];
        float z1 = h_s[ty][i + 1] * We_s[i + 1][tx];
        acc0 += tanh_fast(z0);
        acc1 += tanh_fast(z1);
    }
    h_out[(b0 + ty) * OUT + o0 + tx] = acc0 + acc1 + bias[o0 + tx];
}

// Last layer on the TENSOR pipe: tf32 mma.sync m16n8k8 with hi/lo split
// (D += Ah*Bh + Ah*Bl + Al*Bh; dropped Al*Bl ~ 2^-24 rel).
// CTA: 256 thr (8 warps), covers 32 batches x 64 outputs. grid (64, 2) = 128.
// Warp w: b_sub = (w&1)*16, o_sub = (w>>1)*16 (two n=8 mma tiles).
#define HRS 260   // h smem row stride: frag banks (b*4 + k) all distinct
#define WRS 72    // W smem row stride: frag banks (k*8 + o) all distinct
__global__ __launch_bounds__(256) void layer_lin_mma_kernel(
    const float* __restrict__ h_in,   // [BATCH, 256] fp32
    const float* __restrict__ W2h,    // [256][128] tf32-hi bits
    const float* __restrict__ W2l,    // [256][128] tf32-lo bits
    const float* __restrict__ bias,   // [128]
    float* __restrict__ out) {        // [BATCH, 128]
    constexpr int IN = D2;
    extern __shared__ float sh[];
    float* Hh_s = sh;                          // [32][HRS]
    float* Hl_s = sh + 32 * HRS;               // [32][HRS]
    float* Wh_s = sh + 2 * 32 * HRS;           // [256][WRS]
    float* Wl_s = sh + 2 * 32 * HRS + IN * WRS;// [256][WRS]

    const int tid = threadIdx.x;
    const int lane = tid & 31;
    const int w = tid >> 5;
    const int b0 = blockIdx.x * 32;
    const int obase = blockIdx.y * 64;         // this CTA's 64 output cols

    // Stage h tile [32][256] with tf32 hi/lo split (LDG float4 coalesced).
    for (int idx = tid; idx < 32 * IN / 4; idx += 256) {
        int b = idx >> 6;                      // /64
        int k4 = idx & 63;
        float4 v = *reinterpret_cast<const float4*>(&h_in[(b0 + b) * IN + k4 * 4]);
        float hv[4] = {v.x, v.y, v.z, v.w};
#pragma unroll
        for (int j = 0; j < 4; j++) {
            unsigned int hb = to_tf32(hv[j]);
            float hf = __uint_as_float(hb);
            unsigned int lb = to_tf32(hv[j] - hf);
            Hh_s[b * HRS + k4 * 4 + j] = hf;
            Hl_s[b * HRS + k4 * 4 + j] = __uint_as_float(lb);
        }
    }
    // Stage W halves [256][64] (already split in prep; plain copies, coalesced).
    for (int idx = tid; idx < IN * 16; idx += 256) {   // 16 float4 cols per k-row
        int k = idx >> 4;
        int o4 = idx & 15;
        float4 vh = *reinterpret_cast<const float4*>(&W2h[k * D3 + obase + o4 * 4]);
        float4 vl = *reinterpret_cast<const float4*>(&W2l[k * D3 + obase + o4 * 4]);
        *reinterpret_cast<float4*>(&Wh_s[k * WRS + o4 * 4]) = vh;
        *reinterpret_cast<float4*>(&Wl_s[k * WRS + o4 * 4]) = vl;
    }
    __syncthreads();

    const int b_sub = (w & 1) * 16;
    const int o_sub = (w >> 1) * 16;
    const int g = lane >> 2;          // group 0..7
    const int q = lane & 3;           // 0..3

    float d0[4] = {0.f, 0.f, 0.f, 0.f};   // o-tile 0 (n = o_sub .. o_sub+7)
    float d1[4] = {0.f, 0.f, 0.f, 0.f};   // o-tile 1 (n = o_sub+8 .. +15)

    const float* HhA = Hh_s + (b_sub + g) * HRS;
    const float* HhB = Hh_s + (b_sub + g + 8) * HRS;
    const float* HlA = Hl_s + (b_sub + g) * HRS;
    const float* HlB = Hl_s + (b_sub + g + 8) * HRS;

#pragma unroll 4
    for (int ks = 0; ks < IN / 8; ks++) {
        const int k0 = ks * 8;
        // A fragments (rows b_sub+g / +8, cols k0+q / +4)
        unsigned int ah0 = __float_as_uint(HhA[k0 + q]);
        unsigned int ah1 = __float_as_uint(HhB[k0 + q]);
        unsigned int ah2 = __float_as_uint(HhA[k0 + q + 4]);
        unsigned int ah3 = __float_as_uint(HhB[k0 + q + 4]);
        unsigned int al0 = __float_as_uint(HlA[k0 + q]);
        unsigned int al1 = __float_as_uint(HlB[k0 + q]);
        unsigned int al2 = __float_as_uint(HlA[k0 + q + 4]);
        unsigned int al3 = __float_as_uint(HlB[k0 + q + 4]);
        // B fragments, o-tile 0: rows k0+q / +4, col o_sub+g
        unsigned int bh0 = __float_as_uint(Wh_s[(k0 + q) * WRS + o_sub + g]);
        unsigned int bh1 = __float_as_uint(Wh_s[(k0 + q + 4) * WRS + o_sub + g]);
        unsigned int bl0 = __float_as_uint(Wl_s[(k0 + q) * WRS + o_sub + g]);
        unsigned int bl1 = __float_as_uint(Wl_s[(k0 + q + 4) * WRS + o_sub + g]);
        // B fragments, o-tile 1
        unsigned int ch0 = __float_as_uint(Wh_s[(k0 + q) * WRS + o_sub + 8 + g]);
        unsigned int ch1 = __float_as_uint(Wh_s[(k0 + q + 4) * WRS + o_sub + 8 + g]);
        unsigned int cl0 = __float_as_uint(Wl_s[(k0 + q) * WRS + o_sub + 8 + g]);
        unsigned int cl1 = __float_as_uint(Wl_s[(k0 + q + 4) * WRS + o_sub + 8 + g]);

#define MMA(D, A0, A1, A2, A3, B0, B1)                                          \
        asm("mma.sync.aligned.m16n8k8.row.col.f32.tf32.tf32.f32 "               \
            "{%0,%1,%2,%3}, {%4,%5,%6,%7}, {%8,%9}, {%0,%1,%2,%3};"             \
            : "+f"(D[0]), "+f"(D[1]), "+f"(D[2]), "+f"(D[3])                    \
            : "r"(A0), "r"(A1), "r"(A2), "r"(A3), "r"(B0), "r"(B1))

        MMA(d0, ah0, ah1, ah2, ah3, bh0, bh1);
        MMA(d0, ah0, ah1, ah2, ah3, bl0, bl1);
        MMA(d0, al0, al1, al2, al3, bh0, bh1);
        MMA(d1, ah0, ah1, ah2, ah3, ch0, ch1);
        MMA(d1, ah0, ah1, ah2, ah3, cl0, cl1);
        MMA(d1, al0, al1, al2, al3, ch0, ch1);
#undef MMA
    }

    // Store: D layout — d[0],d[1] at (row = g, col = 2q, 2q+1); d[2],d[3] at row g+8.
    const int row0 = b0 + b_sub + g;
    const int c0 = obase + o_sub + 2 * q;          // o-tile 0
    const int c1 = obase + o_sub + 8 + 2 * q;      // o-tile 1
    float2 bias0 = *reinterpret_cast<const float2*>(&bias[c0]);
    float2 bias1 = *reinterpret_cast<const float2*>(&bias[c1]);
    float2 v;
    v.x = d0[0] + bias0.x; v.y = d0[1] + bias0.y;
    *reinterpret_cast<float2*>(&out[row0 * D3 + c0]) = v;
    v.x = d0[2] + bias0.x; v.y = d0[3] + bias0.y;
    *reinterpret_cast<float2*>(&out[(row0 + 8) * D3 + c0]) = v;
    v.x = d1[0] + bias1.x; v.y = d1[1] + bias1.y;
    *reinterpret_cast<float2*>(&out[row0 * D3 + c1]) = v;
    v.x = d1[2] + bias1.x; v.y = d1[3] + bias1.y;
    *reinterpret_cast<float2*>(&out[(row0 + 8) * D3 + c1]) = v;
}

extern "C" void kernel_launch(void* const* d_in, const int* in_sizes, int n_in,
                              void* d_out, int out_size) {
    // Resolve input ordering at runtime (dict vs signature order).
    const float *x, *W0, *b0, *W1, *b1, *W2, *b2;
    const int *f0, *f1, *f2;
    x = (const float*)d_in[0];
    if (in_sizes[4] == 256) {
        // signature order: x, W0,b0, W1,b1, W2,b2, f0,f1,f2
        W0 = (const float*)d_in[1]; b0 = (const float*)d_in[2];
        W1 = (const float*)d_in[3]; b1 = (const float*)d_in[4];
        W2 = (const float*)d_in[5]; b2 = (const float*)d_in[6];
        f0 = (const int*)d_in[7];  f1 = (const int*)d_in[8];  f2 = (const int*)d_in[9];
    } else {
        // dict order: x, W0,b0,f0, W1,b1,f1, W2,b2,f2
        W0 = (const float*)d_in[1]; b0 = (const float*)d_in[2]; f0 = (const int*)d_in[3];
        W1 = (const float*)d_in[4]; b1 = (const float*)d_in[5]; f1 = (const int*)d_in[6];
        W2 = (const float*)d_in[7]; b2 = (const float*)d_in[8]; f2 = (const int*)d_in[9];
    }

    float *dWe0, *dWe1, *dW2h, *dW2l, *dh1, *dh2;
    cudaGetSymbolAddress((void**)&dWe0, g_We0);
    cudaGetSymbolAddress((void**)&dWe1, g_We1);
    cudaGetSymbolAddress((void**)&dW2h, g_W2h);
    cudaGetSymbolAddress((void**)&dW2l, g_W2l);
    cudaGetSymbolAddress((void**)&dh1, g_h1);
    cudaGetSymbolAddress((void**)&dh2, g_h2);

    float* out = (float*)d_out;

    // Dynamic smem for the mma kernel: 2*32*260 + 2*256*72 floats = 214016 B.
    const int lin_smem = (2 * 32 * HRS + 2 * D2 * WRS) * (int)sizeof(float);
    cudaFuncSetAttribute(layer_lin_mma_kernel,
                         cudaFuncAttributeMaxDynamicSharedMemorySize, lin_smem);

    prep_we_kernel<<<256, 256>>>(W0, f0, W1, f1, W2, f2);

    dim3 blk(32, 8);
    // Layer 0: x -> h1 (MUFU tanh, at floor)
    layer_tanh_kernel<D0><<<dim3(D1 / 32, BATCH / 8), blk>>>(x, dWe0, b0, dh1, D1);
    // Layer 1: h1 -> h2 (MUFU tanh, at floor)
    layer_tanh_kernel<D1><<<dim3(D2 / 32, BATCH / 8), blk>>>(dh1, dWe1, b1, dh2, D2);
    // Layer 2: h2 -> out, tf32 split mma (tensor pipe), grid 64x2 = 128 CTAs
    layer_lin_mma_kernel<<<dim3(BATCH / 32, 2), 256, lin_smem>>>(
        dh2, dW2h, dW2l, b2, out);
}